// round 8
// baseline (speedup 1.0000x reference)
#include <cuda_runtime.h>
#include <cuda_bf16.h>

// KnowledgeRetriever: query [4,1024,512] f32 (dead code), knowledge [64,512] f32.
// Reference's top-64-of-64 argsort selects ALL rows -> output = column-mean of
// knowledge broadcast to every of 4096 output rows.
//
// Single-wave fused kernel, grid (4 colgroups x 64 rowgroups) = 256 blocks,
// 256 threads. Each block: mean of its 32 float4-columns over all 64 knowledge
// rows (32KB L2 reads), then stores a 64-row x 32-float4 output tile (32KB).
// Every warp redundantly reduces the partials in registers -> only ONE barrier
// on the critical path, no shared mean broadcast.

#define E4            128               // float4 per row (E=512)
#define KROWS         64
#define OUT_ROWS      4096              // 4*1024
#define COLS_PER_BLK  32                // float4 columns per block
#define ROWS_PER_BLK  64                // output rows per block (4096/64)
#define THREADS       256

__global__ void __launch_bounds__(THREADS)
kr_fused_kernel(const float* __restrict__ knowledge, float4* __restrict__ out) {
    __shared__ float4 part[8][COLS_PER_BLK];

    const float4* __restrict__ k4 = reinterpret_cast<const float4*>(knowledge);

    const int t       = threadIdx.x;
    const int lane    = t & 31;                    // column within slice
    const int w       = t >> 5;                    // warp id 0..7
    const int colbase = blockIdx.x * COLS_PER_BLK; // 0,32,64,96
    const int rowbase = blockIdx.y * ROWS_PER_BLK; // output row base

    // ---- Partial sums: warp w sums knowledge rows [8w, 8w+8) for its 32 cols.
    {
        float4 s = make_float4(0.f, 0.f, 0.f, 0.f);
        const int r0 = w * 8;
#pragma unroll
        for (int r = 0; r < 8; r++) {
            float4 v = k4[(size_t)(r0 + r) * E4 + colbase + lane];
            s.x += v.x; s.y += v.y; s.z += v.z; s.w += v.w;
        }
        part[w][lane] = s;
    }
    __syncthreads();

    // ---- Redundant per-warp reduce (conflict-free LDS: lane-indexed banks).
    float4 v = make_float4(0.f, 0.f, 0.f, 0.f);
#pragma unroll
    for (int g = 0; g < 8; g++) {
        float4 p = part[g][lane];
        v.x += p.x; v.y += p.y; v.z += p.z; v.w += p.w;
    }
    const float inv = 1.0f / (float)KROWS;
    v.x *= inv; v.y *= inv; v.z *= inv; v.w *= inv;

    // ---- Store phase: warp w writes rows rowbase + w, w+8, ... (8 rows),
    // 512B contiguous per row (lanes cover 32 consecutive float4).
#pragma unroll
    for (int r = 0; r < ROWS_PER_BLK / 8; r++) {
        const int row = rowbase + w + r * 8;
        out[(size_t)row * E4 + colbase + lane] = v;
    }
}

extern "C" void kernel_launch(void* const* d_in, const int* in_sizes, int n_in,
                              void* d_out, int out_size) {
    // d_in[0]: query_embedding (unused — dead code in reference)
    // d_in[1]: knowledge [64,512] f32
    const float* knowledge = (const float*)d_in[1];
    float4* out4 = (float4*)d_out;

    dim3 grid(E4 / COLS_PER_BLK, OUT_ROWS / ROWS_PER_BLK);   // (4, 64) = 256 blocks
    kr_fused_kernel<<<grid, THREADS>>>(knowledge, out4);
}